// round 2
// baseline (speedup 1.0000x reference)
#include <cuda_runtime.h>
#include <cuda.h>
#include <cstdint>

// ---------------- problem constants ----------------
#define NROWS   8192
#define KDIM    4096
#define ODIM    4096

#define BM      128
#define BN      256
#define BK      128                 // int8 elements per k-iter (128 bytes)
#define STAGES  4
#define KIT     (KDIM / BK)         // 32

#define A_BYTES (BM * BK)           // 16384
#define B_BYTES (BN * BK)           // 32768
#define STAGE_BYTES (A_BYTES + B_BYTES)      // 49152
#define SMEM_CTRL 1024
#define SMEM_SIZE (SMEM_CTRL + STAGES * STAGE_BYTES) // 197632

#define FULL_OFF(s)  ((s) * 8)
#define EMPTY_OFF(s) (64 + (s) * 8)
#define STAGE_OFF(s) (SMEM_CTRL + (s) * STAGE_BYTES)

// ---------------- device scratch (allocation-free rule) ----------------
__device__ __align__(1024) uint8_t g_bx[(size_t)NROWS * KDIM]; // s8 +-1
__device__ __align__(1024) uint8_t g_bw[(size_t)ODIM * KDIM];

// ---------------- PTX helpers (all non-arch-specific: sm_90 base ok) ---
__device__ __forceinline__ uint32_t smem_u32(const void* p) {
    uint32_t a;
    asm("{ .reg .u64 t; cvta.to.shared.u64 t, %1; cvt.u32.u64 %0, t; }" : "=r"(a) : "l"(p));
    return a;
}

#define MBARRIER_INIT(addr, cnt) \
    asm volatile("mbarrier.init.shared.b64 [%0], %1;" :: "r"(addr), "r"(cnt) : "memory")

#define MBARRIER_EXPECT_TX(addr, bytes) \
    asm volatile("mbarrier.arrive.expect_tx.shared.b64 _, [%0], %1;" \
                 :: "r"(addr), "r"(bytes) : "memory")

#define MBARRIER_ARRIVE(addr) \
    asm volatile("mbarrier.arrive.shared.b64 _, [%0];" :: "r"(addr) : "memory")

#define MBARRIER_WAIT_PARITY(addr, parity) do {                                   \
    uint32_t _m = (addr); uint32_t _p = (parity); uint32_t _d;                    \
    asm volatile("{\n\t.reg .pred p;\n\t"                                         \
        "mbarrier.try_wait.parity.acquire.cta.shared::cta.b64 p, [%1], %2;\n\t"   \
        "selp.b32 %0, 1, 0, p;\n\t}"                                              \
        : "=r"(_d) : "r"(_m), "r"(_p) : "memory");                                \
    if (!_d) {                                                                    \
        asm volatile("{\n\t.reg .pred P1;\n\t"                                    \
            "WL_%=:\n\t"                                                          \
            "mbarrier.try_wait.parity.acquire.cta.shared::cta.b64 P1, [%0], %1, 0x989680;\n\t" \
            "@P1 bra.uni WD_%=;\n\t"                                              \
            "bra.uni WL_%=;\n\t"                                                  \
            "WD_%=:\n\t}"                                                         \
            :: "r"(_m), "r"(_p) : "memory");                                      \
    }                                                                             \
} while (0)

#define TMA_LOAD_3D(smem_addr, tmap, cx, cy, cz, mbar)                            \
    asm volatile("cp.async.bulk.tensor.3d.shared::cta.global.tile.mbarrier::complete_tx::bytes " \
                 "[%0], [%1, {%2, %3, %4}], [%5];"                                \
                 :: "r"((uint32_t)(smem_addr)), "l"(tmap),                        \
                    "r"((int32_t)(cx)), "r"((int32_t)(cy)), "r"((int32_t)(cz)),   \
                    "r"((uint32_t)(mbar)) : "memory")

__device__ __forceinline__ void ldsm4(uint32_t* r, uint32_t addr) {
    asm volatile("ldmatrix.sync.aligned.m8n8.x4.shared.b16 {%0,%1,%2,%3}, [%4];"
        : "=r"(r[0]), "=r"(r[1]), "=r"(r[2]), "=r"(r[3]) : "r"(addr));
}

__device__ __forceinline__ void mma_s8(uint32_t* d, const uint32_t* a,
                                       uint32_t b0, uint32_t b1) {
    asm volatile("mma.sync.aligned.m16n8k32.row.col.s32.s8.s8.s32 "
        "{%0,%1,%2,%3}, {%4,%5,%6,%7}, {%8,%9}, {%0,%1,%2,%3};"
        : "+r"(d[0]), "+r"(d[1]), "+r"(d[2]), "+r"(d[3])
        : "r"(a[0]), "r"(a[1]), "r"(a[2]), "r"(a[3]), "r"(b0), "r"(b1));
}

// ---------------- pack kernel: f32 -> s8 sign(+-1), 16 floats/thread ---
__device__ __forceinline__ uint32_t sgnb(uint32_t v) {
    // byte 0x01 if v >= 0 (ieee sign bit 0), 0xFF if negative
    return (uint32_t)((((int32_t)v) >> 31) | 1) & 0xFFu;
}
__global__ void __launch_bounds__(256) pack_sign(const uint4* __restrict__ in,
                                                 uint4* __restrict__ out, int n16) {
    int i = blockIdx.x * blockDim.x + threadIdx.x;
    if (i >= n16) return;
    uint4 o;
    uint4 v0 = in[i * 4 + 0];
    uint4 v1 = in[i * 4 + 1];
    uint4 v2 = in[i * 4 + 2];
    uint4 v3 = in[i * 4 + 3];
    o.x = sgnb(v0.x) | (sgnb(v0.y) << 8) | (sgnb(v0.z) << 16) | (sgnb(v0.w) << 24);
    o.y = sgnb(v1.x) | (sgnb(v1.y) << 8) | (sgnb(v1.z) << 16) | (sgnb(v1.w) << 24);
    o.z = sgnb(v2.x) | (sgnb(v2.y) << 8) | (sgnb(v2.z) << 16) | (sgnb(v2.w) << 24);
    o.w = sgnb(v3.x) | (sgnb(v3.y) << 8) | (sgnb(v3.z) << 16) | (sgnb(v3.w) << 24);
    out[i] = o;
}

// ---------------- int8 IMMA GEMM ----------------
__global__ void __launch_bounds__(256, 1) bgemm_kernel(
    const __grid_constant__ CUtensorMap tma_a,
    const __grid_constant__ CUtensorMap tma_b,
    const float* __restrict__ bias,
    float* __restrict__ out)
{
    extern __shared__ __align__(1024) uint8_t smem[];
    const uint32_t sb = smem_u32(smem);
    const int tid  = threadIdx.x;
    const int wid  = tid >> 5;
    const int lane = tid & 31;

    // tile swizzle for L2: groups of 8 mt x 16 nt
    const int bid = blockIdx.x;
    const int mt  = (bid >> 7) * 8 + (bid & 7);
    const int nt  = (bid >> 3) & 15;

    // warps: 2 (m) x 4 (n); warp tile 64x64
    const int wm = (wid & 1) * 64;
    const int wn = (wid >> 1) * 64;

    if (tid == 0) {
        #pragma unroll
        for (int s = 0; s < STAGES; s++) {
            MBARRIER_INIT(sb + FULL_OFF(s), 1);
            MBARRIER_INIT(sb + EMPTY_OFF(s), 8);
        }
    }
    __syncthreads();

    // prologue: prefill 3 stages
    if (tid == 0) {
        #pragma unroll
        for (int s = 0; s < 3; s++) {
            uint32_t full = sb + FULL_OFF(s);
            MBARRIER_EXPECT_TX(full, (uint32_t)STAGE_BYTES);
            TMA_LOAD_3D(sb + STAGE_OFF(s),           &tma_a, s * BK, mt * BM, 0, full);
            TMA_LOAD_3D(sb + STAGE_OFF(s) + A_BYTES, &tma_b, s * BK, nt * BN, 0, full);
        }
    }

    // per-thread ldmatrix base offsets (SW128 swizzle folds to a constant XOR)
    // A: matrices per m16 tile: (rows0-7,c0),(rows8-15,c0),(rows0-7,c16),(rows8-15,c16)
    const int rA   = wm + (lane & 7) + ((lane >> 3) & 1) * 8;
    const int cA   = ((lane >> 4) & 1) * 16;
    const uint32_t swzA  = (uint32_t)((rA & 7) << 4);
    const uint32_t aRow  = (uint32_t)(rA * BK);
    // B: matrices per n-pair: (n0-7,c0),(n0-7,c16),(n8-15,c0),(n8-15,c16)
    const int rB   = wn + (lane & 7) + ((lane >> 4) & 1) * 8;
    const int cB   = ((lane >> 3) & 1) * 16;
    const uint32_t swzB  = (uint32_t)((rB & 7) << 4);
    const uint32_t bRow  = (uint32_t)(rB * BK);

    uint32_t acc[4][8][4];
    #pragma unroll
    for (int mi = 0; mi < 4; mi++)
        #pragma unroll
        for (int ni = 0; ni < 8; ni++)
            #pragma unroll
            for (int q = 0; q < 4; q++) acc[mi][ni][q] = 0;

    #pragma unroll 1
    for (int kit = 0; kit < KIT; kit++) {
        const int s  = kit & 3;
        const int ph = (kit >> 2) & 1;

        // producer: issue load for kit+3
        if (tid == 0) {
            const int kl = kit + 3;
            if (kl < KIT) {
                const int sl = kl & 3;
                const int rl = kl >> 2;
                if (rl > 0) MBARRIER_WAIT_PARITY(sb + EMPTY_OFF(sl), (rl - 1) & 1);
                uint32_t full = sb + FULL_OFF(sl);
                MBARRIER_EXPECT_TX(full, (uint32_t)STAGE_BYTES);
                TMA_LOAD_3D(sb + STAGE_OFF(sl),           &tma_a, kl * BK, mt * BM, 0, full);
                TMA_LOAD_3D(sb + STAGE_OFF(sl) + A_BYTES, &tma_b, kl * BK, nt * BN, 0, full);
            }
        }

        MBARRIER_WAIT_PARITY(sb + FULL_OFF(s), ph);

        const uint32_t sA = sb + STAGE_OFF(s) + aRow;
        const uint32_t sB = sb + STAGE_OFF(s) + A_BYTES + bRow;

        #pragma unroll
        for (int ks = 0; ks < 4; ks++) {
            uint32_t aF[4][4];
            uint32_t bF[4][4];
            #pragma unroll
            for (int mi = 0; mi < 4; mi++)
                ldsm4(aF[mi], sA + mi * (16 * BK) + (((uint32_t)(cA + ks * 32)) ^ swzA));
            #pragma unroll
            for (int np = 0; np < 4; np++)
                ldsm4(bF[np], sB + np * (16 * BK) + (((uint32_t)(cB + ks * 32)) ^ swzB));
            #pragma unroll
            for (int ni = 0; ni < 8; ni++)
                #pragma unroll
                for (int mi = 0; mi < 4; mi++)
                    mma_s8(acc[mi][ni], aF[mi], bF[ni >> 1][(ni & 1) * 2],
                                                 bF[ni >> 1][(ni & 1) * 2 + 1]);
        }

        if (lane == 0) MBARRIER_ARRIVE(sb + EMPTY_OFF(s));
    }

    // ---------------- epilogue: s32 -> f32 + bias ----------------
    const int colBase = nt * BN + wn + (lane & 3) * 2;
    const int rowBase = mt * BM + wm + (lane >> 2);

    float2 b2[8];
    #pragma unroll
    for (int ni = 0; ni < 8; ni++)
        b2[ni] = *reinterpret_cast<const float2*>(bias + colBase + ni * 8);

    #pragma unroll
    for (int mi = 0; mi < 4; mi++) {
        const int r0 = rowBase + mi * 16;
        float* p0 = out + (size_t)r0 * ODIM + colBase;
        float* p1 = out + (size_t)(r0 + 8) * ODIM + colBase;
        #pragma unroll
        for (int ni = 0; ni < 8; ni++) {
            float2 v0, v1;
            v0.x = (float)(int)acc[mi][ni][0] + b2[ni].x;
            v0.y = (float)(int)acc[mi][ni][1] + b2[ni].y;
            v1.x = (float)(int)acc[mi][ni][2] + b2[ni].x;
            v1.y = (float)(int)acc[mi][ni][3] + b2[ni].y;
            *reinterpret_cast<float2*>(p0 + ni * 8) = v0;
            *reinterpret_cast<float2*>(p1 + ni * 8) = v1;
        }
    }
}

// ---------------- host ----------------
typedef CUresult (*EncodeFn)(CUtensorMap*, CUtensorMapDataType, cuuint32_t, void*,
                             const cuuint64_t*, const cuuint64_t*, const cuuint32_t*,
                             const cuuint32_t*, CUtensorMapInterleave, CUtensorMapSwizzle,
                             CUtensorMapL2promotion, CUtensorMapFloatOOBfill);

extern "C" void kernel_launch(void* const* d_in, const int* in_sizes, int n_in,
                              void* d_out, int out_size) {
    const float* x    = (const float*)d_in[0];
    const float* w    = (const float*)d_in[1];
    const float* bias = (const float*)d_in[2];
    float* out = (float*)d_out;

    void* pbx = nullptr; cudaGetSymbolAddress(&pbx, g_bx);
    void* pbw = nullptr; cudaGetSymbolAddress(&pbw, g_bw);

    // pack f32 -> s8 signs (16 floats per thread)
    const int nx16 = in_sizes[0] / 16;
    const int nw16 = in_sizes[1] / 16;
    pack_sign<<<(nx16 + 255) / 256, 256>>>((const uint4*)x, (uint4*)pbx, nx16);
    pack_sign<<<(nw16 + 255) / 256, 256>>>((const uint4*)w, (uint4*)pbw, nw16);

    // tensormaps via driver entry point
    EncodeFn enc = nullptr;
    {
        void* fp = nullptr;
        cudaDriverEntryPointQueryResult st;
        cudaGetDriverEntryPoint("cuTensorMapEncodeTiled", &fp, cudaEnableDefault, &st);
        enc = (EncodeFn)fp;
    }
    if (!enc) return;

    CUtensorMap ta, tb;
    {
        cuuint64_t dims[3]    = {KDIM, NROWS, 1};
        cuuint64_t strides[2] = {KDIM, (cuuint64_t)KDIM * NROWS};
        cuuint32_t box[3]     = {BK, BM, 1};
        cuuint32_t es[3]      = {1, 1, 1};
        enc(&ta, CU_TENSOR_MAP_DATA_TYPE_UINT8, 3, pbx, dims, strides, box, es,
            CU_TENSOR_MAP_INTERLEAVE_NONE, CU_TENSOR_MAP_SWIZZLE_128B,
            CU_TENSOR_MAP_L2_PROMOTION_L2_128B, CU_TENSOR_MAP_FLOAT_OOB_FILL_NONE);
    }
    {
        cuuint64_t dims[3]    = {KDIM, ODIM, 1};
        cuuint64_t strides[2] = {KDIM, (cuuint64_t)KDIM * ODIM};
        cuuint32_t box[3]     = {BK, BN, 1};
        cuuint32_t es[3]      = {1, 1, 1};
        enc(&tb, CU_TENSOR_MAP_DATA_TYPE_UINT8, 3, pbw, dims, strides, box, es,
            CU_TENSOR_MAP_INTERLEAVE_NONE, CU_TENSOR_MAP_SWIZZLE_128B,
            CU_TENSOR_MAP_L2_PROMOTION_L2_128B, CU_TENSOR_MAP_FLOAT_OOB_FILL_NONE);
    }

    cudaFuncSetAttribute(bgemm_kernel, cudaFuncAttributeMaxDynamicSharedMemorySize, SMEM_SIZE);

    const int grid = (NROWS / BM) * (ODIM / BN);  // 64 * 16 = 1024
    bgemm_kernel<<<grid, 256, SMEM_SIZE>>>(ta, tb, bias, out);
}

// round 3
// speedup vs baseline: 1.0096x; 1.0096x over previous
#include <cuda_runtime.h>
#include <cuda.h>
#include <cstdint>

// ---------------- problem constants ----------------
#define NROWS   8192
#define KDIM    4096
#define ODIM    4096

#define BM      128
#define BN      256
#define BK      128                 // int8 elements per k-iter (128 bytes)
#define STAGES  4
#define KIT     (KDIM / BK)         // 32
#define NTHREADS 512

#define A_BYTES (BM * BK)           // 16384
#define B_BYTES (BN * BK)           // 32768
#define STAGE_BYTES (A_BYTES + B_BYTES)      // 49152
#define SMEM_CTRL 1024
#define SMEM_SIZE (SMEM_CTRL + STAGES * STAGE_BYTES) // 197632

#define FULL_OFF(s)  ((s) * 8)
#define EMPTY_OFF(s) (64 + (s) * 8)
#define STAGE_OFF(s) (SMEM_CTRL + (s) * STAGE_BYTES)

// ---------------- device scratch (allocation-free rule) ----------------
__device__ __align__(1024) uint8_t g_bx[(size_t)NROWS * KDIM]; // s8 +-1
__device__ __align__(1024) uint8_t g_bw[(size_t)ODIM * KDIM];

// ---------------- PTX helpers ----------------
__device__ __forceinline__ uint32_t smem_u32(const void* p) {
    uint32_t a;
    asm("{ .reg .u64 t; cvta.to.shared.u64 t, %1; cvt.u32.u64 %0, t; }" : "=r"(a) : "l"(p));
    return a;
}

#define MBARRIER_INIT(addr, cnt) \
    asm volatile("mbarrier.init.shared.b64 [%0], %1;" :: "r"(addr), "r"(cnt) : "memory")

#define MBARRIER_EXPECT_TX(addr, bytes) \
    asm volatile("mbarrier.arrive.expect_tx.shared.b64 _, [%0], %1;" \
                 :: "r"(addr), "r"(bytes) : "memory")

#define MBARRIER_ARRIVE(addr) \
    asm volatile("mbarrier.arrive.shared.b64 _, [%0];" :: "r"(addr) : "memory")

#define MBARRIER_WAIT_PARITY(addr, parity) do {                                   \
    uint32_t _m = (addr); uint32_t _p = (parity); uint32_t _d;                    \
    asm volatile("{\n\t.reg .pred p;\n\t"                                         \
        "mbarrier.try_wait.parity.acquire.cta.shared::cta.b64 p, [%1], %2;\n\t"   \
        "selp.b32 %0, 1, 0, p;\n\t}"                                              \
        : "=r"(_d) : "r"(_m), "r"(_p) : "memory");                                \
    if (!_d) {                                                                    \
        asm volatile("{\n\t.reg .pred P1;\n\t"                                    \
            "WL_%=:\n\t"                                                          \
            "mbarrier.try_wait.parity.acquire.cta.shared::cta.b64 P1, [%0], %1, 0x989680;\n\t" \
            "@P1 bra.uni WD_%=;\n\t"                                              \
            "bra.uni WL_%=;\n\t"                                                  \
            "WD_%=:\n\t}"                                                         \
            :: "r"(_m), "r"(_p) : "memory");                                      \
    }                                                                             \
} while (0)

#define TMA_LOAD_3D(smem_addr, tmap, cx, cy, cz, mbar)                            \
    asm volatile("cp.async.bulk.tensor.3d.shared::cta.global.tile.mbarrier::complete_tx::bytes " \
                 "[%0], [%1, {%2, %3, %4}], [%5];"                                \
                 :: "r"((uint32_t)(smem_addr)), "l"(tmap),                        \
                    "r"((int32_t)(cx)), "r"((int32_t)(cy)), "r"((int32_t)(cz)),   \
                    "r"((uint32_t)(mbar)) : "memory")

__device__ __forceinline__ void ldsm4(uint32_t* r, uint32_t addr) {
    asm volatile("ldmatrix.sync.aligned.m8n8.x4.shared.b16 {%0,%1,%2,%3}, [%4];"
        : "=r"(r[0]), "=r"(r[1]), "=r"(r[2]), "=r"(r[3]) : "r"(addr));
}

__device__ __forceinline__ void mma_s8(uint32_t* d, const uint32_t* a,
                                       uint32_t b0, uint32_t b1) {
    asm volatile("mma.sync.aligned.m16n8k32.row.col.s32.s8.s8.s32 "
        "{%0,%1,%2,%3}, {%4,%5,%6,%7}, {%8,%9}, {%0,%1,%2,%3};"
        : "+r"(d[0]), "+r"(d[1]), "+r"(d[2]), "+r"(d[3])
        : "r"(a[0]), "r"(a[1]), "r"(a[2]), "r"(a[3]), "r"(b0), "r"(b1));
}

// ---------------- pack kernel: f32 -> s8 sign(+-1), 16 floats/thread ---
__device__ __forceinline__ uint32_t sgnb(uint32_t v) {
    return (uint32_t)((((int32_t)v) >> 31) | 1) & 0xFFu;
}
__global__ void __launch_bounds__(256) pack_sign(const uint4* __restrict__ in,
                                                 uint4* __restrict__ out, int n16) {
    int i = blockIdx.x * blockDim.x + threadIdx.x;
    if (i >= n16) return;
    uint4 o;
    uint4 v0 = in[i * 4 + 0];
    uint4 v1 = in[i * 4 + 1];
    uint4 v2 = in[i * 4 + 2];
    uint4 v3 = in[i * 4 + 3];
    o.x = sgnb(v0.x) | (sgnb(v0.y) << 8) | (sgnb(v0.z) << 16) | (sgnb(v0.w) << 24);
    o.y = sgnb(v1.x) | (sgnb(v1.y) << 8) | (sgnb(v1.z) << 16) | (sgnb(v1.w) << 24);
    o.z = sgnb(v2.x) | (sgnb(v2.y) << 8) | (sgnb(v2.z) << 16) | (sgnb(v2.w) << 24);
    o.w = sgnb(v3.x) | (sgnb(v3.y) << 8) | (sgnb(v3.z) << 16) | (sgnb(v3.w) << 24);
    out[i] = o;
}

// ---------------- int8 IMMA GEMM: 512 threads, warp tile 64x32 ----------
__global__ void __launch_bounds__(NTHREADS, 1) bgemm_kernel(
    const __grid_constant__ CUtensorMap tma_a,
    const __grid_constant__ CUtensorMap tma_b,
    const float* __restrict__ bias,
    float* __restrict__ out)
{
    extern __shared__ __align__(1024) uint8_t smem[];
    const uint32_t sb = smem_u32(smem);
    const int tid  = threadIdx.x;
    const int wid  = tid >> 5;
    const int lane = tid & 31;

    // tile swizzle for L2: groups of 8 mt x 16 nt
    const int bid = blockIdx.x;
    const int mt  = (bid >> 7) * 8 + (bid & 7);
    const int nt  = (bid >> 3) & 15;

    // 16 warps: 2 (m) x 8 (n); warp tile 64x32
    const int wm = (wid & 1) * 64;
    const int wn = (wid >> 1) * 32;

    if (tid == 0) {
        #pragma unroll
        for (int s = 0; s < STAGES; s++) {
            MBARRIER_INIT(sb + FULL_OFF(s), 1);
            MBARRIER_INIT(sb + EMPTY_OFF(s), 16);
        }
    }
    __syncthreads();

    // prologue: prefill 3 stages
    if (tid == 0) {
        #pragma unroll
        for (int s = 0; s < 3; s++) {
            uint32_t full = sb + FULL_OFF(s);
            MBARRIER_EXPECT_TX(full, (uint32_t)STAGE_BYTES);
            TMA_LOAD_3D(sb + STAGE_OFF(s),           &tma_a, s * BK, mt * BM, 0, full);
            TMA_LOAD_3D(sb + STAGE_OFF(s) + A_BYTES, &tma_b, s * BK, nt * BN, 0, full);
        }
    }

    // per-thread ldmatrix base offsets (SW128 swizzle folds to constant XOR)
    const int rA   = wm + (lane & 7) + ((lane >> 3) & 1) * 8;
    const int cA   = ((lane >> 4) & 1) * 16;
    const uint32_t swzA  = (uint32_t)((rA & 7) << 4);
    const uint32_t aRow  = (uint32_t)(rA * BK);
    const int rB   = wn + (lane & 7) + ((lane >> 4) & 1) * 8;
    const int cB   = ((lane >> 3) & 1) * 16;
    const uint32_t swzB  = (uint32_t)((rB & 7) << 4);
    const uint32_t bRow  = (uint32_t)(rB * BK);

    uint32_t acc[4][4][4];
    #pragma unroll
    for (int mi = 0; mi < 4; mi++)
        #pragma unroll
        for (int ni = 0; ni < 4; ni++)
            #pragma unroll
            for (int q = 0; q < 4; q++) acc[mi][ni][q] = 0;

    #pragma unroll 1
    for (int kit = 0; kit < KIT; kit++) {
        const int s  = kit & 3;
        const int ph = (kit >> 2) & 1;

        // producer: issue load for kit+3
        if (tid == 0) {
            const int kl = kit + 3;
            if (kl < KIT) {
                const int sl = kl & 3;
                const int rl = kl >> 2;
                if (rl > 0) MBARRIER_WAIT_PARITY(sb + EMPTY_OFF(sl), (rl - 1) & 1);
                uint32_t full = sb + FULL_OFF(sl);
                MBARRIER_EXPECT_TX(full, (uint32_t)STAGE_BYTES);
                TMA_LOAD_3D(sb + STAGE_OFF(sl),           &tma_a, kl * BK, mt * BM, 0, full);
                TMA_LOAD_3D(sb + STAGE_OFF(sl) + A_BYTES, &tma_b, kl * BK, nt * BN, 0, full);
            }
        }

        MBARRIER_WAIT_PARITY(sb + FULL_OFF(s), ph);

        const uint32_t sA = sb + STAGE_OFF(s) + aRow;
        const uint32_t sB = sb + STAGE_OFF(s) + A_BYTES + bRow;

        #pragma unroll
        for (int ks = 0; ks < 4; ks++) {
            uint32_t aF[4][4];
            uint32_t bF[2][4];
            #pragma unroll
            for (int mi = 0; mi < 4; mi++)
                ldsm4(aF[mi], sA + mi * (16 * BK) + (((uint32_t)(cA + ks * 32)) ^ swzA));
            #pragma unroll
            for (int np = 0; np < 2; np++)
                ldsm4(bF[np], sB + np * (16 * BK) + (((uint32_t)(cB + ks * 32)) ^ swzB));
            #pragma unroll
            for (int ni = 0; ni < 4; ni++)
                #pragma unroll
                for (int mi = 0; mi < 4; mi++)
                    mma_s8(acc[mi][ni], aF[mi], bF[ni >> 1][(ni & 1) * 2],
                                                 bF[ni >> 1][(ni & 1) * 2 + 1]);
        }

        if (lane == 0) MBARRIER_ARRIVE(sb + EMPTY_OFF(s));
    }

    // ---------------- epilogue: s32 -> f32 + bias ----------------
    const int colBase = nt * BN + wn + (lane & 3) * 2;
    const int rowBase = mt * BM + wm + (lane >> 2);

    float2 b2[4];
    #pragma unroll
    for (int ni = 0; ni < 4; ni++)
        b2[ni] = *reinterpret_cast<const float2*>(bias + colBase + ni * 8);

    #pragma unroll
    for (int mi = 0; mi < 4; mi++) {
        const int r0 = rowBase + mi * 16;
        float* p0 = out + (size_t)r0 * ODIM + colBase;
        float* p1 = out + (size_t)(r0 + 8) * ODIM + colBase;
        #pragma unroll
        for (int ni = 0; ni < 4; ni++) {
            float2 v0, v1;
            v0.x = (float)(int)acc[mi][ni][0] + b2[ni].x;
            v0.y = (float)(int)acc[mi][ni][1] + b2[ni].y;
            v1.x = (float)(int)acc[mi][ni][2] + b2[ni].x;
            v1.y = (float)(int)acc[mi][ni][3] + b2[ni].y;
            *reinterpret_cast<float2*>(p0 + ni * 8) = v0;
            *reinterpret_cast<float2*>(p1 + ni * 8) = v1;
        }
    }
}

// ---------------- host ----------------
typedef CUresult (*EncodeFn)(CUtensorMap*, CUtensorMapDataType, cuuint32_t, void*,
                             const cuuint64_t*, const cuuint64_t*, const cuuint32_t*,
                             const cuuint32_t*, CUtensorMapInterleave, CUtensorMapSwizzle,
                             CUtensorMapL2promotion, CUtensorMapFloatOOBfill);

extern "C" void kernel_launch(void* const* d_in, const int* in_sizes, int n_in,
                              void* d_out, int out_size) {
    const float* x    = (const float*)d_in[0];
    const float* w    = (const float*)d_in[1];
    const float* bias = (const float*)d_in[2];
    float* out = (float*)d_out;

    void* pbx = nullptr; cudaGetSymbolAddress(&pbx, g_bx);
    void* pbw = nullptr; cudaGetSymbolAddress(&pbw, g_bw);

    const int nx16 = in_sizes[0] / 16;
    const int nw16 = in_sizes[1] / 16;
    pack_sign<<<(nx16 + 255) / 256, 256>>>((const uint4*)x, (uint4*)pbx, nx16);
    pack_sign<<<(nw16 + 255) / 256, 256>>>((const uint4*)w, (uint4*)pbw, nw16);

    EncodeFn enc = nullptr;
    {
        void* fp = nullptr;
        cudaDriverEntryPointQueryResult st;
        cudaGetDriverEntryPoint("cuTensorMapEncodeTiled", &fp, cudaEnableDefault, &st);
        enc = (EncodeFn)fp;
    }
    if (!enc) return;

    CUtensorMap ta, tb;
    {
        cuuint64_t dims[3]    = {KDIM, NROWS, 1};
        cuuint64_t strides[2] = {KDIM, (cuuint64_t)KDIM * NROWS};
        cuuint32_t box[3]     = {BK, BM, 1};
        cuuint32_t es[3]      = {1, 1, 1};
        enc(&ta, CU_TENSOR_MAP_DATA_TYPE_UINT8, 3, pbx, dims, strides, box, es,
            CU_TENSOR_MAP_INTERLEAVE_NONE, CU_TENSOR_MAP_SWIZZLE_128B,
            CU_TENSOR_MAP_L2_PROMOTION_L2_128B, CU_TENSOR_MAP_FLOAT_OOB_FILL_NONE);
    }
    {
        cuuint64_t dims[3]    = {KDIM, ODIM, 1};
        cuuint64_t strides[2] = {KDIM, (cuuint64_t)KDIM * ODIM};
        cuuint32_t box[3]     = {BK, BN, 1};
        cuuint32_t es[3]      = {1, 1, 1};
        enc(&tb, CU_TENSOR_MAP_DATA_TYPE_UINT8, 3, pbw, dims, strides, box, es,
            CU_TENSOR_MAP_INTERLEAVE_NONE, CU_TENSOR_MAP_SWIZZLE_128B,
            CU_TENSOR_MAP_L2_PROMOTION_L2_128B, CU_TENSOR_MAP_FLOAT_OOB_FILL_NONE);
    }

    cudaFuncSetAttribute(bgemm_kernel, cudaFuncAttributeMaxDynamicSharedMemorySize, SMEM_SIZE);

    const int grid = (NROWS / BM) * (ODIM / BN);  // 64 * 16 = 1024
    bgemm_kernel<<<grid, NTHREADS, SMEM_SIZE>>>(ta, tb, bias, out);
}

// round 4
// speedup vs baseline: 1.9492x; 1.9306x over previous
#include <cuda_runtime.h>
#include <cstdint>

// ---------------- problem constants ----------------
#define NROWS   8192
#define KDIM    4096
#define ODIM    4096
#define KW      (KDIM / 32)        // 128 words of packed sign bits per row
#define TW      128                // output tile: 128 x 128
#define CHUNK   16                 // k-words per pipeline stage
#define KITC    (KW / CHUNK)       // 8 chunks
#define GSTAGES 4
#define STAGE_WORDS (2 * CHUNK * TW)            // A + B: 4096 words = 16KB
#define SMEM_BYTES  (GSTAGES * STAGE_WORDS * 4) // 65536

// ---------------- device scratch (allocation-free rule) ----------------
// transposed bit-planes: g_xT[kw][n], g_wT[kw][o]
__device__ __align__(1024) uint32_t g_xT[(size_t)KW * NROWS];
__device__ __align__(1024) uint32_t g_wT[(size_t)KW * ODIM];

// ---------------- helpers ----------------
__device__ __forceinline__ uint32_t smem_u32(const void* p) {
    uint32_t a;
    asm("{ .reg .u64 t; cvta.to.shared.u64 t, %1; cvt.u32.u64 %0, t; }" : "=r"(a) : "l"(p));
    return a;
}
#define CP_ASYNC16(dst, src) \
    asm volatile("cp.async.cg.shared.global [%0], [%1], 16;" :: "r"(dst), "l"(src))
#define CP_COMMIT() asm volatile("cp.async.commit_group;" ::: "memory")
#define CP_WAIT3()  asm volatile("cp.async.wait_group 3;"  ::: "memory")

// ---------------- pack: f32 -> 1 bit sign, transposed [kw][row] ---------
// bit i of word (kw, n) = sign bit of in[n][kw*32 + i]  (1 = negative = -1)
__global__ void __launch_bounds__(256) pack_bits(const float4* __restrict__ in,
                                                 uint32_t* __restrict__ outT,
                                                 int nShift) {
    const int idx = blockIdx.x * 256 + threadIdx.x;
    const int n   = idx & ((1 << nShift) - 1);
    const int kw  = idx >> nShift;
    const float4* p = in + (size_t)n * (KDIM / 4) + kw * 8;
    uint32_t w = 0;
    #pragma unroll
    for (int j = 0; j < 8; j++) {
        float4 v = p[j];
        w |= (__float_as_uint(v.x) >> 31) << (4 * j);
        w |= (__float_as_uint(v.y) >> 31) << (4 * j + 1);
        w |= (__float_as_uint(v.z) >> 31) << (4 * j + 2);
        w |= (__float_as_uint(v.w) >> 31) << (4 * j + 3);
    }
    outT[idx] = w;
}

// ---------------- XNOR-popcount GEMM ----------------
// out[n][o] = 4096 - 2 * sum_kw popc(xT[kw][n] ^ wT[kw][o]) + bias[o]
__global__ void __launch_bounds__(256, 2) xnor_gemm(
    const uint32_t* __restrict__ xT, const uint32_t* __restrict__ wT,
    const float* __restrict__ bias, float* __restrict__ out)
{
    extern __shared__ __align__(16) uint32_t sm[];
    const uint32_t smBase = smem_u32(sm);
    const int tid = threadIdx.x;
    const int tx  = tid & 15;        // 16 col groups
    const int ty  = tid >> 4;        // 16 row groups
    const int mt  = blockIdx.x & 63; // 64 m tiles
    const int nt  = blockIdx.x >> 6; // 32 n tiles
    const int mBase = mt * TW;
    const int nBase = nt * TW;

    // -------- producer: 4 x 16B cp.async per thread per stage --------
    auto load_stage = [&](int s, int c) {
        #pragma unroll
        for (int k = 0; k < 4; k++) {
            const int ch  = tid + k * 256;   // 0..1023
            const int tsr = ch >> 9;         // 0 = A(x), 1 = B(w)
            const int rem = ch & 511;
            const int kw  = rem >> 5;        // 0..15
            const int nq  = rem & 31;        // 16B chunk within 128 words
            const uint32_t* gsrc = tsr
                ? (wT + (size_t)(c * CHUNK + kw) * ODIM  + nBase + nq * 4)
                : (xT + (size_t)(c * CHUNK + kw) * NROWS + mBase + nq * 4);
            const uint32_t dst = smBase +
                (uint32_t)((s * STAGE_WORDS + tsr * (CHUNK * TW) + kw * TW + nq * 4) * 4);
            CP_ASYNC16(dst, gsrc);
        }
    };

    int acc[8][8];
    #pragma unroll
    for (int r = 0; r < 8; r++)
        #pragma unroll
        for (int c = 0; c < 8; c++) acc[r][c] = 0;

    // prologue: 3 stages in flight
    #pragma unroll
    for (int s = 0; s < 3; s++) { load_stage(s, s); CP_COMMIT(); }

    #pragma unroll 1
    for (int c = 0; c < KITC; c++) {
        const int cl = c + 3;
        if (cl < KITC) load_stage(cl & 3, cl);
        CP_COMMIT();                 // always commit (empty group on tail)
        CP_WAIT3();                  // groups <= c complete -> stage c ready
        __syncthreads();

        const uint32_t* As = sm + (c & 3) * STAGE_WORDS;
        const uint32_t* Bs = As + CHUNK * TW;

        #pragma unroll 1
        for (int kw = 0; kw < CHUNK; kw += 2) {
            uint4 a00 = *reinterpret_cast<const uint4*>(As + kw * TW + ty * 8);
            uint4 a01 = *reinterpret_cast<const uint4*>(As + kw * TW + ty * 8 + 4);
            uint4 a10 = *reinterpret_cast<const uint4*>(As + (kw + 1) * TW + ty * 8);
            uint4 a11 = *reinterpret_cast<const uint4*>(As + (kw + 1) * TW + ty * 8 + 4);
            uint4 b00 = *reinterpret_cast<const uint4*>(Bs + kw * TW + tx * 8);
            uint4 b01 = *reinterpret_cast<const uint4*>(Bs + kw * TW + tx * 8 + 4);
            uint4 b10 = *reinterpret_cast<const uint4*>(Bs + (kw + 1) * TW + tx * 8);
            uint4 b11 = *reinterpret_cast<const uint4*>(Bs + (kw + 1) * TW + tx * 8 + 4);

            uint32_t A0[8] = {a00.x, a00.y, a00.z, a00.w, a01.x, a01.y, a01.z, a01.w};
            uint32_t A1[8] = {a10.x, a10.y, a10.z, a10.w, a11.x, a11.y, a11.z, a11.w};
            uint32_t B0[8] = {b00.x, b00.y, b00.z, b00.w, b01.x, b01.y, b01.z, b01.w};
            uint32_t B1[8] = {b10.x, b10.y, b10.z, b10.w, b11.x, b11.y, b11.z, b11.w};

            #pragma unroll
            for (int r = 0; r < 8; r++)
                #pragma unroll
                for (int cc = 0; cc < 8; cc++)
                    acc[r][cc] += __popc(A0[r] ^ B0[cc]) + __popc(A1[r] ^ B1[cc]);
        }
        __syncthreads();             // before stage buffer gets overwritten
    }

    // -------- epilogue: out = 4096 - 2*acc + bias --------
    const int rb = mBase + ty * 8;
    const int cb = nBase + tx * 8;
    const float4 bias0 = *reinterpret_cast<const float4*>(bias + cb);
    const float4 bias1 = *reinterpret_cast<const float4*>(bias + cb + 4);

    #pragma unroll
    for (int r = 0; r < 8; r++) {
        float4 o0, o1;
        o0.x = (float)(KDIM - 2 * acc[r][0]) + bias0.x;
        o0.y = (float)(KDIM - 2 * acc[r][1]) + bias0.y;
        o0.z = (float)(KDIM - 2 * acc[r][2]) + bias0.z;
        o0.w = (float)(KDIM - 2 * acc[r][3]) + bias0.w;
        o1.x = (float)(KDIM - 2 * acc[r][4]) + bias1.x;
        o1.y = (float)(KDIM - 2 * acc[r][5]) + bias1.y;
        o1.z = (float)(KDIM - 2 * acc[r][6]) + bias1.z;
        o1.w = (float)(KDIM - 2 * acc[r][7]) + bias1.w;
        float* po = out + (size_t)(rb + r) * ODIM + cb;
        *reinterpret_cast<float4*>(po)     = o0;
        *reinterpret_cast<float4*>(po + 4) = o1;
    }
}

// ---------------- host ----------------
extern "C" void kernel_launch(void* const* d_in, const int* in_sizes, int n_in,
                              void* d_out, int out_size) {
    const float* x    = (const float*)d_in[0];
    const float* w    = (const float*)d_in[1];
    const float* bias = (const float*)d_in[2];
    float* out = (float*)d_out;

    void* pxT = nullptr; cudaGetSymbolAddress(&pxT, g_xT);
    void* pwT = nullptr; cudaGetSymbolAddress(&pwT, g_wT);

    // pack both operands into transposed bit-planes
    pack_bits<<<(KW * NROWS) / 256, 256>>>((const float4*)x, (uint32_t*)pxT, 13); // n in [0,8192)
    pack_bits<<<(KW * ODIM) / 256, 256>>>((const float4*)w, (uint32_t*)pwT, 12);  // o in [0,4096)

    cudaFuncSetAttribute(xnor_gemm, cudaFuncAttributeMaxDynamicSharedMemorySize, SMEM_BYTES);

    const int grid = (NROWS / TW) * (ODIM / TW);   // 64 * 32 = 2048
    xnor_gemm<<<grid, 256, SMEM_BYTES>>>((const uint32_t*)pxT, (const uint32_t*)pwT,
                                         bias, out);
}

// round 5
// speedup vs baseline: 2.6464x; 1.3577x over previous
#include <cuda_runtime.h>
#include <cstdint>

// ---------------- problem constants ----------------
#define NROWS   8192
#define KDIM    4096
#define ODIM    4096
#define KW      (KDIM / 32)        // 128 words of packed sign bits per row
#define TW      128                // output tile: 128 x 128
#define CHUNK   16                 // k-words per pipeline stage
#define KITC    (KW / CHUNK)       // 8 chunks
#define GSTAGES 4
#define STAGE_WORDS (2 * CHUNK * TW)            // A + B: 4096 words = 16KB
#define SMEM_BYTES  (GSTAGES * STAGE_WORDS * 4) // 65536

// ---------------- device scratch (allocation-free rule) ----------------
__device__ __align__(1024) uint32_t g_xT[(size_t)KW * NROWS];
__device__ __align__(1024) uint32_t g_wT[(size_t)KW * ODIM];

// ---------------- helpers ----------------
__device__ __forceinline__ uint32_t smem_u32(const void* p) {
    uint32_t a;
    asm("{ .reg .u64 t; cvta.to.shared.u64 t, %1; cvt.u32.u64 %0, t; }" : "=r"(a) : "l"(p));
    return a;
}
#define CP_ASYNC16(dst, src) \
    asm volatile("cp.async.cg.shared.global [%0], [%1], 16;" :: "r"(dst), "l"(src))
#define CP_COMMIT() asm volatile("cp.async.commit_group;" ::: "memory")
#define CP_WAIT3()  asm volatile("cp.async.wait_group 3;"  ::: "memory")

__device__ __forceinline__ uint32_t xor3(uint32_t a, uint32_t b, uint32_t c) {
    uint32_t d; asm("lop3.b32 %0, %1, %2, %3, 0x96;" : "=r"(d) : "r"(a), "r"(b), "r"(c));
    return d;
}
__device__ __forceinline__ uint32_t maj3(uint32_t a, uint32_t b, uint32_t c) {
    uint32_t d; asm("lop3.b32 %0, %1, %2, %3, 0xE8;" : "=r"(d) : "r"(a), "r"(b), "r"(c));
    return d;
}

// ---------------- pack: f32 -> 1 bit sign, transposed [kw][row] ---------
__global__ void __launch_bounds__(256) pack_bits(const float4* __restrict__ in,
                                                 uint32_t* __restrict__ outT,
                                                 int nShift) {
    const int idx = blockIdx.x * 256 + threadIdx.x;
    const int n   = idx & ((1 << nShift) - 1);
    const int kw  = idx >> nShift;
    const float4* p = in + (size_t)n * (KDIM / 4) + kw * 8;
    uint32_t w = 0;
    #pragma unroll
    for (int j = 0; j < 8; j++) {
        float4 v = p[j];
        w |= (__float_as_uint(v.x) >> 31) << (4 * j);
        w |= (__float_as_uint(v.y) >> 31) << (4 * j + 1);
        w |= (__float_as_uint(v.z) >> 31) << (4 * j + 2);
        w |= (__float_as_uint(v.w) >> 31) << (4 * j + 3);
    }
    outT[idx] = w;
}

// ---------------- XNOR-popcount GEMM with 8:4 CSA compression ----------
// out[n][o] = 4096 - 2 * sum_kw popc(xT[kw][n] ^ wT[kw][o]) + bias[o]
__global__ void __launch_bounds__(256, 1) xnor_gemm(
    const uint32_t* __restrict__ xT, const uint32_t* __restrict__ wT,
    const float* __restrict__ bias, float* __restrict__ out)
{
    extern __shared__ __align__(16) uint32_t sm[];
    const uint32_t smBase = smem_u32(sm);
    const int tid = threadIdx.x;
    const int tx  = tid & 15;        // 16 col groups
    const int ty  = tid >> 4;        // 16 row groups
    const int mt  = blockIdx.x & 63;
    const int nt  = blockIdx.x >> 6;
    const int mBase = mt * TW;
    const int nBase = nt * TW;

    auto load_stage = [&](int s, int c) {
        #pragma unroll
        for (int k = 0; k < 4; k++) {
            const int ch  = tid + k * 256;
            const int tsr = ch >> 9;
            const int rem = ch & 511;
            const int kw  = rem >> 5;
            const int nq  = rem & 31;
            const uint32_t* gsrc = tsr
                ? (wT + (size_t)(c * CHUNK + kw) * ODIM  + nBase + nq * 4)
                : (xT + (size_t)(c * CHUNK + kw) * NROWS + mBase + nq * 4);
            const uint32_t dst = smBase +
                (uint32_t)((s * STAGE_WORDS + tsr * (CHUNK * TW) + kw * TW + nq * 4) * 4);
            CP_ASYNC16(dst, gsrc);
        }
    };

    int acc[8][8];
    #pragma unroll
    for (int r = 0; r < 8; r++)
        #pragma unroll
        for (int c = 0; c < 8; c++) acc[r][c] = 0;

    #pragma unroll
    for (int s = 0; s < 3; s++) { load_stage(s, s); CP_COMMIT(); }

    #pragma unroll 1
    for (int c = 0; c < KITC; c++) {
        const int cl = c + 3;
        if (cl < KITC) load_stage(cl & 3, cl);
        CP_COMMIT();
        CP_WAIT3();
        __syncthreads();

        const uint32_t* As = sm + (c & 3) * STAGE_WORDS;
        const uint32_t* Bs = As + CHUNK * TW;

        // two groups of 8 k-words, each compressed 8 -> 4 popc via CSA tree
        #pragma unroll
        for (int g = 0; g < 2; g++) {
            const int kb = g * 8;

            // B fragments: Bf[k][cc] for this thread's 8 columns
            uint32_t Bf[8][8];
            #pragma unroll
            for (int k = 0; k < 8; k++) {
                uint4 u0 = *reinterpret_cast<const uint4*>(Bs + (kb + k) * TW + tx * 8);
                uint4 u1 = *reinterpret_cast<const uint4*>(Bs + (kb + k) * TW + tx * 8 + 4);
                Bf[k][0] = u0.x; Bf[k][1] = u0.y; Bf[k][2] = u0.z; Bf[k][3] = u0.w;
                Bf[k][4] = u1.x; Bf[k][5] = u1.y; Bf[k][6] = u1.z; Bf[k][7] = u1.w;
            }

            // process rows in two halves of 4 to bound A-fragment liveness
            #pragma unroll
            for (int rr = 0; rr < 2; rr++) {
                uint32_t Af[8][4];
                #pragma unroll
                for (int k = 0; k < 8; k++) {
                    uint4 u = *reinterpret_cast<const uint4*>(
                        As + (kb + k) * TW + ty * 8 + rr * 4);
                    Af[k][0] = u.x; Af[k][1] = u.y; Af[k][2] = u.z; Af[k][3] = u.w;
                }
                #pragma unroll
                for (int r = 0; r < 4; r++) {
                    #pragma unroll
                    for (int cc = 0; cc < 8; cc++) {
                        const uint32_t x0 = Af[0][r] ^ Bf[0][cc];
                        const uint32_t x1 = Af[1][r] ^ Bf[1][cc];
                        const uint32_t x2 = Af[2][r] ^ Bf[2][cc];
                        const uint32_t x3 = Af[3][r] ^ Bf[3][cc];
                        const uint32_t x4 = Af[4][r] ^ Bf[4][cc];
                        const uint32_t x5 = Af[5][r] ^ Bf[5][cc];
                        const uint32_t x6 = Af[6][r] ^ Bf[6][cc];
                        const uint32_t x7 = Af[7][r] ^ Bf[7][cc];
                        // CSA 8 -> 4: T = popc(S) + 2(popc(S2)+popc(C3)) + 4 popc(C2)
                        const uint32_t s0 = xor3(x0, x1, x2), c0 = maj3(x0, x1, x2);
                        const uint32_t s1 = xor3(x3, x4, x5), c1 = maj3(x3, x4, x5);
                        const uint32_t s2 = x6 ^ x7,          c2 = x6 & x7;
                        const uint32_t S  = xor3(s0, s1, s2), C3 = maj3(s0, s1, s2);
                        const uint32_t S2 = xor3(c0, c1, c2), C2 = maj3(c0, c1, c2);
                        acc[rr * 4 + r][cc] += __popc(S)
                                             + 2 * (__popc(S2) + __popc(C3))
                                             + 4 * __popc(C2);
                    }
                }
            }
        }
        __syncthreads();
    }

    // -------- epilogue: out = 4096 - 2*acc + bias --------
    const int rb = mBase + ty * 8;
    const int cb = nBase + tx * 8;
    const float4 bias0 = *reinterpret_cast<const float4*>(bias + cb);
    const float4 bias1 = *reinterpret_cast<const float4*>(bias + cb + 4);

    #pragma unroll
    for (int r = 0; r < 8; r++) {
        float4 o0, o1;
        o0.x = (float)(KDIM - 2 * acc[r][0]) + bias0.x;
        o0.y = (float)(KDIM - 2 * acc[r][1]) + bias0.y;
        o0.z = (float)(KDIM - 2 * acc[r][2]) + bias0.z;
        o0.w = (float)(KDIM - 2 * acc[r][3]) + bias0.w;
        o1.x = (float)(KDIM - 2 * acc[r][4]) + bias1.x;
        o1.y = (float)(KDIM - 2 * acc[r][5]) + bias1.y;
        o1.z = (float)(KDIM - 2 * acc[r][6]) + bias1.z;
        o1.w = (float)(KDIM - 2 * acc[r][7]) + bias1.w;
        float* po = out + (size_t)(rb + r) * ODIM + cb;
        *reinterpret_cast<float4*>(po)     = o0;
        *reinterpret_cast<float4*>(po + 4) = o1;
    }
}

// ---------------- host ----------------
extern "C" void kernel_launch(void* const* d_in, const int* in_sizes, int n_in,
                              void* d_out, int out_size) {
    const float* x    = (const float*)d_in[0];
    const float* w    = (const float*)d_in[1];
    const float* bias = (const float*)d_in[2];
    float* out = (float*)d_out;

    void* pxT = nullptr; cudaGetSymbolAddress(&pxT, g_xT);
    void* pwT = nullptr; cudaGetSymbolAddress(&pwT, g_wT);

    pack_bits<<<(KW * NROWS) / 256, 256>>>((const float4*)x, (uint32_t*)pxT, 13);
    pack_bits<<<(KW * ODIM) / 256, 256>>>((const float4*)w, (uint32_t*)pwT, 12);

    cudaFuncSetAttribute(xnor_gemm, cudaFuncAttributeMaxDynamicSharedMemorySize, SMEM_BYTES);

    const int grid = (NROWS / TW) * (ODIM / TW);   // 2048
    xnor_gemm<<<grid, 256, SMEM_BYTES>>>((const uint32_t*)pxT, (const uint32_t*)pwT,
                                         bias, out);
}